// round 1
// baseline (speedup 1.0000x reference)
#include <cuda_runtime.h>
#include <math.h>

// Problem constants
#define BSZ   4096
#define ADIM  256          // alphabet / decoder hidden
#define TDIM  128          // tag dim
#define NSTEP 30
#define PROBS_STRIDE (31*256)                 // per-batch stride in probabilities [B,31,A]
#define PROBS_TOTAL  (4096*31*256)

// ---------------- device state (no allocations allowed) ----------------
// Double-buffered hidden/cell state per layer: g_h[parity][layer][B*256]
__device__ float g_h[2][3][BSZ*ADIM];
__device__ float g_c[2][3][BSZ*ADIM];
// Precomputed layer-0 constant contribution: tags@Wih0[:,256:].T + bih0 + bhh0, [B,1024]
__device__ float g_pre0[BSZ*1024];

__device__ __forceinline__ float sigf(float x) { return 1.0f / (1.0f + expf(-x)); }

// ---------------- init kernels ----------------
__global__ void init_state_kernel() {
    int i = blockIdx.x * blockDim.x + threadIdx.x;
    const int N = 3 * BSZ * ADIM;
    if (i < N) {
        int l = i / (BSZ * ADIM);
        int r = i % (BSZ * ADIM);
        g_h[0][l][r] = 0.f;
        g_c[0][l][r] = 0.f;
    }
}

// probabilities[:,0,:] = one-hot(START=1)
__global__ void start_kernel(float* __restrict__ d_out) {
    int i = blockIdx.x * blockDim.x + threadIdx.x;
    if (i < BSZ * ADIM) {
        int b = i >> 8;
        int a = i & 255;
        d_out[b * PROBS_STRIDE + a] = (a == 1) ? 1.0f : 0.0f;
    }
}

// ---------------- pre0: [4096x128] x [128x1024] (tags part of Wih0) ----------------
__global__ __launch_bounds__(256) void pre0_kernel(
    const float* __restrict__ tags, const float* __restrict__ Wih0,
    const float* __restrict__ bih0, const float* __restrict__ bhh0)
{
    __shared__ float As[16][68];   // [k][r]
    __shared__ float Bs[16][68];   // [k][c]
    int tid = threadIdx.x;
    int tx = tid & 15, ty = tid >> 4;
    int r0 = blockIdx.x * 64, j0 = blockIdx.y * 64;
    float acc[4][4];
#pragma unroll
    for (int i = 0; i < 4; i++)
#pragma unroll
        for (int j = 0; j < 4; j++) acc[i][j] = 0.f;

    for (int k0 = 0; k0 < TDIM; k0 += 16) {
#pragma unroll
        for (int it = 0; it < 4; it++) {
            int i = it * 256 + tid; int r = i >> 4, k = i & 15;
            As[k][r] = tags[(r0 + r) * TDIM + k0 + k];
        }
#pragma unroll
        for (int it = 0; it < 4; it++) {
            int i = it * 256 + tid; int c = i >> 4, k = i & 15;
            Bs[k][c] = Wih0[(j0 + c) * 384 + 256 + k0 + k];
        }
        __syncthreads();
#pragma unroll
        for (int k = 0; k < 16; k++) {
            float a[4], b[4];
            *(float4*)a = *(const float4*)&As[k][ty * 4];
            *(float4*)b = *(const float4*)&Bs[k][tx * 4];
#pragma unroll
            for (int i = 0; i < 4; i++)
#pragma unroll
                for (int j = 0; j < 4; j++) acc[i][j] += a[i] * b[j];
        }
        __syncthreads();
    }
#pragma unroll
    for (int i = 0; i < 4; i++)
#pragma unroll
        for (int j = 0; j < 4; j++) {
            int r = r0 + ty * 4 + i, c = j0 + tx * 4 + j;
            g_pre0[r * 1024 + c] = acc[i][j] + bih0[c] + bhh0[c];
        }
}

// ---------------- fused LSTM layer: G = X@Wx^T + H@Wh^T (+pre/bias), cell update ----------------
// Tile: 128 batch rows x 16 hidden units (=> 64 gate columns: 4 gates per unit, thread-local).
__global__ __launch_bounds__(256) void lstm_kernel(
    const float* __restrict__ Xptr, int ldx, int xsel,
    const float* __restrict__ Wx, int ldwx,
    const float* __restrict__ Wh,
    const float* __restrict__ b1, const float* __restrict__ b2,
    int use_pre, int layer, int par)
{
    const float* X = (xsel >= 0) ? g_h[par ^ 1][xsel] : Xptr;
    if (xsel >= 0) ldx = ADIM;
    const float* H   = g_h[par][layer];
    const float* Cin = g_c[par][layer];
    float* Hout = g_h[par ^ 1][layer];
    float* Cout = g_c[par ^ 1][layer];

    __shared__ float As[16][132];  // [k][row], padded
    __shared__ float Bs[16][68];   // [k][uu*4+g], padded

    int tid = threadIdx.x;
    int tx = tid & 15, ty = tid >> 4;
    int row0 = blockIdx.x * 128;
    int u0 = blockIdx.y * 16;

    float acc[8][4];
#pragma unroll
    for (int i = 0; i < 8; i++)
#pragma unroll
        for (int g = 0; g < 4; g++) acc[i][g] = 0.f;

    for (int k0 = 0; k0 < 512; k0 += 16) {
        const float* A; int lda, kc;
        const float* W; int ldw;
        if (k0 < 256) { A = X; lda = ldx;  kc = k0;       W = Wx; ldw = ldwx; }
        else          { A = H; lda = ADIM; kc = k0 - 256; W = Wh; ldw = ADIM; }
#pragma unroll
        for (int it = 0; it < 8; it++) {               // 128x16 A tile
            int i = it * 256 + tid; int r = i >> 4, k = i & 15;
            As[k][r] = A[(row0 + r) * lda + kc + k];
        }
#pragma unroll
        for (int it = 0; it < 4; it++) {               // 64x16 W tile (4 gate groups)
            int i = it * 256 + tid; int c = i >> 4, k = i & 15;
            int uu = c & 15, g = c >> 4;
            Bs[k][uu * 4 + g] = W[(g * 256 + u0 + uu) * ldw + kc + k];
        }
        __syncthreads();
#pragma unroll
        for (int k = 0; k < 16; k++) {
            float a[8], b[4];
            *(float4*)&a[0] = *(const float4*)&As[k][ty * 8];
            *(float4*)&a[4] = *(const float4*)&As[k][ty * 8 + 4];
            *(float4*)&b[0] = *(const float4*)&Bs[k][tx * 4];
#pragma unroll
            for (int i = 0; i < 8; i++)
#pragma unroll
                for (int g = 0; g < 4; g++) acc[i][g] += a[i] * b[g];
        }
        __syncthreads();
    }

    // epilogue: torch gate order i,f,g,o
    int u = u0 + tx;
    float bb0 = 0.f, bb1 = 0.f, bb2 = 0.f, bb3 = 0.f;
    if (!use_pre) {
        bb0 = b1[0 * 256 + u] + b2[0 * 256 + u];
        bb1 = b1[1 * 256 + u] + b2[1 * 256 + u];
        bb2 = b1[2 * 256 + u] + b2[2 * 256 + u];
        bb3 = b1[3 * 256 + u] + b2[3 * 256 + u];
    }
#pragma unroll
    for (int i = 0; i < 8; i++) {
        int r = row0 + ty * 8 + i;
        float p0, p1, p2, p3;
        if (use_pre) {
            p0 = g_pre0[r * 1024 + 0   + u];
            p1 = g_pre0[r * 1024 + 256 + u];
            p2 = g_pre0[r * 1024 + 512 + u];
            p3 = g_pre0[r * 1024 + 768 + u];
        } else { p0 = bb0; p1 = bb1; p2 = bb2; p3 = bb3; }
        float gi = sigf(acc[i][0] + p0);
        float gf = sigf(acc[i][1] + p1);
        float gg = tanhf(acc[i][2] + p2);
        float go = sigf(acc[i][3] + p3);
        float c  = Cin[r * ADIM + u];
        float cn = gf * c + gi * gg;
        Cout[r * ADIM + u] = cn;
        Hout[r * ADIM + u] = go * tanhf(cn);
    }
}

// ---------------- output linear: pred = sigmoid(h2 @ linW^T + b) -> probs slice s+1 ----------------
__global__ __launch_bounds__(256) void linear_kernel(
    const float* __restrict__ linW, const float* __restrict__ linb,
    float* __restrict__ d_out, int s, int par)
{
    const float* H2 = g_h[par ^ 1][2];
    __shared__ float As[16][68];
    __shared__ float Bs[16][68];
    int tid = threadIdx.x;
    int tx = tid & 15, ty = tid >> 4;
    int r0 = blockIdx.x * 64, c0 = blockIdx.y * 64;
    float acc[4][4];
#pragma unroll
    for (int i = 0; i < 4; i++)
#pragma unroll
        for (int j = 0; j < 4; j++) acc[i][j] = 0.f;

    for (int k0 = 0; k0 < 256; k0 += 16) {
#pragma unroll
        for (int it = 0; it < 4; it++) {
            int i = it * 256 + tid; int r = i >> 4, k = i & 15;
            As[k][r] = H2[(r0 + r) * 256 + k0 + k];
        }
#pragma unroll
        for (int it = 0; it < 4; it++) {
            int i = it * 256 + tid; int c = i >> 4, k = i & 15;
            Bs[k][c] = linW[(c0 + c) * 256 + k0 + k];
        }
        __syncthreads();
#pragma unroll
        for (int k = 0; k < 16; k++) {
            float a[4], b[4];
            *(float4*)a = *(const float4*)&As[k][ty * 4];
            *(float4*)b = *(const float4*)&Bs[k][tx * 4];
#pragma unroll
            for (int i = 0; i < 4; i++)
#pragma unroll
                for (int j = 0; j < 4; j++) acc[i][j] += a[i] * b[j];
        }
        __syncthreads();
    }
#pragma unroll
    for (int i = 0; i < 4; i++)
#pragma unroll
        for (int j = 0; j < 4; j++) {
            int r = r0 + ty * 4 + i, c = c0 + tx * 4 + j;
            d_out[(r * 31 + s + 1) * 256 + c] = sigf(acc[i][j] + linb[c]);
        }
}

// ---------------- argmax over 256 classes, first-max semantics (matches jnp.argmax) ----------------
__global__ void argmax_kernel(const float* __restrict__ d_probs, float* __restrict__ outs, int s) {
    int warp = (blockIdx.x * blockDim.x + threadIdx.x) >> 5;
    int lane = threadIdx.x & 31;
    if (warp >= BSZ) return;
    const float* row = d_probs + (warp * 31 + s + 1) * 256;
    float best = -1e30f; int bi = 0;
#pragma unroll
    for (int j = 0; j < 8; j++) {
        int c = lane + j * 32;           // ascending per lane -> strict '>' keeps first
        float v = row[c];
        if (v > best) { best = v; bi = c; }
    }
#pragma unroll
    for (int off = 16; off; off >>= 1) {
        float ov = __shfl_xor_sync(0xffffffffu, best, off);
        int   oi = __shfl_xor_sync(0xffffffffu, bi, off);
        if (ov > best || (ov == best && oi < bi)) { best = ov; bi = oi; }
    }
    if (lane == 0) outs[warp * NSTEP + s] = (float)bi;
}

// ---------------- launch ----------------
extern "C" void kernel_launch(void* const* d_in, const int* in_sizes, int n_in,
                              void* d_out_v, int out_size)
{
    // metadata order (reference signature order):
    // 0 families, 1 languages, 2 tags, 3 lemmata, 4 emb,
    // 5..12 encoder l1_* (DEAD CODE: encoder output unused by reference outputs),
    // 13 l2_Wih0 [1024,384], 14 l2_Whh0 [1024,256], 15 l2_bih0, 16 l2_bhh0,
    // 17 l2_Wih [2,1024,256], 18 l2_Whh [2,1024,256], 19 l2_bih [2,1024], 20 l2_bhh [2,1024],
    // 21 lin_W [256,256], 22 lin_b [256]
    const float* tags = (const float*)d_in[2];
    const float* Wih0 = (const float*)d_in[13];
    const float* Whh0 = (const float*)d_in[14];
    const float* bih0 = (const float*)d_in[15];
    const float* bhh0 = (const float*)d_in[16];
    const float* Wih  = (const float*)d_in[17];
    const float* Whh  = (const float*)d_in[18];
    const float* bih  = (const float*)d_in[19];
    const float* bhh  = (const float*)d_in[20];
    const float* linW = (const float*)d_in[21];
    const float* linb = (const float*)d_in[22];
    float* d_out = (float*)d_out_v;

    bool has_outputs = (out_size >= PROBS_TOTAL + BSZ * NSTEP);

    init_state_kernel<<<(3 * BSZ * ADIM + 255) / 256, 256>>>();
    start_kernel<<<(BSZ * ADIM + 255) / 256, 256>>>(d_out);
    pre0_kernel<<<dim3(BSZ / 64, 1024 / 64), 256>>>(tags, Wih0, bih0, bhh0);

    for (int s = 0; s < NSTEP; s++) {
        int par = s & 1;
        // layer 0: X = probabilities[:, s, :] from d_out, tags+bias folded into g_pre0
        lstm_kernel<<<dim3(BSZ / 128, 16), 256>>>(
            d_out + s * 256, PROBS_STRIDE, -1,
            Wih0, 384, Whh0, nullptr, nullptr, 1, 0, par);
        // layer 1: X = new h0
        lstm_kernel<<<dim3(BSZ / 128, 16), 256>>>(
            nullptr, 0, 0,
            Wih, 256, Whh, bih, bhh, 0, 1, par);
        // layer 2: X = new h1
        lstm_kernel<<<dim3(BSZ / 128, 16), 256>>>(
            nullptr, 0, 1,
            Wih + 1024 * 256, 256, Whh + 1024 * 256, bih + 1024, bhh + 1024, 0, 2, par);
        // pred -> probabilities[:, s+1, :]
        linear_kernel<<<dim3(BSZ / 64, 4), 256>>>(linW, linb, d_out, s, par);
        if (has_outputs) {
            argmax_kernel<<<(BSZ * 32 + 255) / 256, 256>>>(d_out, d_out + PROBS_TOTAL, s);
        }
    }
}